// round 5
// baseline (speedup 1.0000x reference)
#include <cuda_runtime.h>
#include <math.h>

// FNO spectral conv: truncated separable DFTs + mirror symmetries.
// B=8, H=W=256, CIN=COUT=32, M1=M2=16.
typedef unsigned long long u64;
typedef ulonglong2 u64x2;

// Tables / transposed weights / scratch (device globals).
__device__ __align__(16) float4 g_tab4[256];    // (cos, cos, sin, sin)
__device__ __align__(8)  float2 g_tab2[256];    // (cos, sin)
__device__ __align__(16) float  g_wtr[524288];  // [blk][m1][kx][ci][co]
__device__ __align__(16) float  g_wti[524288];
__device__ __align__(16) float  g_Tre[1048576]; // [b][kx][h][c]
__device__ __align__(16) float  g_Tim[1048576];
__device__ __align__(16) float  g_Xre[131072];  // [p*16+kx][b*32+c]
__device__ __align__(16) float  g_Xim[131072];
__device__ __align__(16) float  g_Yre[131072];  // [p*16+kx][b*32+co]
__device__ __align__(16) float  g_Yim[131072];
__device__ __align__(16) float  g_Gre[1048576]; // [b][h][kx][co]
__device__ __align__(16) float  g_Gim[1048576];

__device__ __forceinline__ u64 pack2(float lo, float hi) {
    u64 r; asm("mov.b64 %0,{%1,%2};" : "=l"(r) : "f"(lo), "f"(hi)); return r;
}
__device__ __forceinline__ float2 unpack2(u64 v) {
    float2 f; asm("mov.b64 {%0,%1},%2;" : "=f"(f.x), "=f"(f.y) : "l"(v)); return f;
}
__device__ __forceinline__ u64 ffma2(u64 a, u64 b, u64 c) {
    u64 d; asm("fma.rn.f32x2 %0,%1,%2,%3;" : "=l"(d) : "l"(a), "l"(b), "l"(c)); return d;
}
__device__ __forceinline__ u64 fmul2(u64 a, u64 b) {
    u64 d; asm("mul.rn.f32x2 %0,%1,%2;" : "=l"(d) : "l"(a), "l"(b)); return d;
}

// ---------------------------------------------------------------------------
// KA: fused launch.
//   blocks [0,4096):    forward w-DFT, one (b,h) row x 16-channel half each.
//   blocks [4096,4608): tiled weight transpose -> [blk][m1][kx][ci][co].
//   block  4608:        twiddle tables for later kernels.
// 128 threads each.
// ---------------------------------------------------------------------------
__global__ __launch_bounds__(128) void kA(const float* __restrict__ x,
                                          const float* __restrict__ wr,
                                          const float* __restrict__ wi) {
    const int bid = blockIdx.x, t = threadIdx.x;

    if (bid < 4096) {
        // ---- forward DFT over w with real-input mirror symmetry ----
        __shared__ __align__(16) float2 se[128 * 8], so[128 * 8];
        __shared__ __align__(16) float4 stab[256];
        __shared__ __align__(16) float2 sx0[8], sx128[8];
        const int row = bid >> 1, cb = (bid & 1) * 16;  // (b*256+h), channel half
        const float* xb = x + (size_t)row * 8192 + cb;

        for (int i = t; i < 256; i += 128) {
            float s, c; sincospif((float)i * (1.0f / 128.0f), &s, &c);
            stab[i] = make_float4(c, c, s, s);
        }
        for (int i = t; i < 1016; i += 128) {
            const int w = 1 + (i >> 3), cp = i & 7;
            const float2 a = *(const float2*)&xb[w * 32 + 2 * cp];
            const float2 b = *(const float2*)&xb[(256 - w) * 32 + 2 * cp];
            se[w * 8 + cp] = make_float2(a.x + b.x, a.y + b.y);
            so[w * 8 + cp] = make_float2(a.x - b.x, a.y - b.y);
        }
        if (t < 8) {
            sx0[t]   = *(const float2*)&xb[2 * t];
            sx128[t] = *(const float2*)&xb[4096 + 2 * t];
        }
        __syncthreads();

        const int kx = t >> 3, cp = t & 7;
        const float sg = (kx & 1) ? -1.0f : 1.0f;
        const u64 sg2 = pack2(sg, sg);
        u64 re = ffma2(*(const u64*)&sx128[cp], sg2, *(const u64*)&sx0[cp]);
        u64 im = 0;
        int m = kx;
#pragma unroll 4
        for (int w = 1; w < 128; w++) {
            const u64 ev = *(const u64*)&se[w * 8 + cp];
            const u64 ov = *(const u64*)&so[w * 8 + cp];
            const u64x2 tv = *(const u64x2*)&stab[m];
            m = (m + kx) & 255;
            re = ffma2(ev, tv.x, re);
            im = ffma2(ov, tv.y, im);
        }
        const int b_ = row >> 8, h = row & 255;
        const size_t idx = ((size_t)((b_ * 16 + kx) * 256 + h)) * 32 + cb + 2 * cp;
        *(float2*)&g_Tre[idx] = unpack2(re);
        *(float2*)&g_Tim[idx] = unpack2(fmul2(im, pack2(-1.0f, -1.0f)));

    } else if (bid < 4608) {
        // ---- tiled transpose: [ci*32+co][m1*16+kx] -> [m1*16+kx][ci*32+co] ----
        __shared__ float sw[32][33], sv[32][33];
        const int tt = bid - 4096;
        const int blkw = tt >> 8, tile = tt & 255;
        const int tr = tile >> 3, tc = tile & 7;   // row tile (1024/32), col tile (256/32)
        const int rr = t >> 5, c = t & 31;
        const float* srcR = wr + blkw * 262144;
        const float* srcI = wi + blkw * 262144;
#pragma unroll
        for (int ph = 0; ph < 8; ph++) {
            const int rl = ph * 4 + rr;
            const int row = tr * 32 + rl, col = tc * 32 + c;
            sw[rl][c] = srcR[row * 256 + col];
            sv[rl][c] = srcI[row * 256 + col];
        }
        __syncthreads();
        float* dR = g_wtr + blkw * 262144;
        float* dI = g_wti + blkw * 262144;
#pragma unroll
        for (int ph = 0; ph < 8; ph++) {
            const int cl = ph * 4 + rr;
            const int dcol = tc * 32 + cl, drow = tr * 32 + c;
            dR[dcol * 1024 + drow] = sw[c][cl];
            dI[dcol * 1024 + drow] = sv[c][cl];
        }
    } else {
        // ---- twiddle tables ----
        for (int i = t; i < 256; i += 128) {
            float s, c; sincospif((float)i * (1.0f / 128.0f), &s, &c);
            g_tab4[i] = make_float4(c, c, s, s);
            g_tab2[i] = make_float2(c, s);
        }
    }
}

// ---------------------------------------------------------------------------
// K2: forward DFT over h (32 kept modes), complex mirror symmetry.
// f = p (p<16) or p+224 (= p-32 mod 256) for high block.
// grid (16 kx, 4 ch, 8 b) = 512 blocks, 128 threads: p(32) x cpair(4).
// ---------------------------------------------------------------------------
__global__ __launch_bounds__(128) void k2_dft_h() {
    __shared__ __align__(16) float4 sA[128 * 4];   // {Er0,Er1,Oi0,Oi1}
    __shared__ __align__(16) float4 sB[128 * 4];   // {Ei0,Ei1,-Or0,-Or1}
    __shared__ __align__(16) float4 stab[256];
    __shared__ __align__(16) float4 sT0[4], sT128[4];
    const int t = threadIdx.x;
    const int kx = blockIdx.x, ch = blockIdx.y, b = blockIdx.z;
    const float* srcR = g_Tre + ((size_t)(b * 16 + kx) * 256) * 32 + ch * 8;
    const float* srcI = g_Tim + ((size_t)(b * 16 + kx) * 256) * 32 + ch * 8;

    for (int i = t; i < 256; i += 128) stab[i] = g_tab4[i];
    for (int i = t; i < 508; i += 128) {
        const int h = 1 + (i >> 2), cp = i & 3;
        const float2 ar = *(const float2*)&srcR[h * 32 + cp * 2];
        const float2 br = *(const float2*)&srcR[(256 - h) * 32 + cp * 2];
        const float2 ai = *(const float2*)&srcI[h * 32 + cp * 2];
        const float2 bi = *(const float2*)&srcI[(256 - h) * 32 + cp * 2];
        sA[(h << 2) + cp] = make_float4(ar.x + br.x, ar.y + br.y, ai.x - bi.x, ai.y - bi.y);
        sB[(h << 2) + cp] = make_float4(ai.x + bi.x, ai.y + bi.y, br.x - ar.x, br.y - ar.y);
    }
    if (t < 4) {
        sT0[t]   = make_float4(srcR[t * 2], srcR[t * 2 + 1], srcI[t * 2], srcI[t * 2 + 1]);
        sT128[t] = make_float4(srcR[4096 + t * 2], srcR[4096 + t * 2 + 1],
                               srcI[4096 + t * 2], srcI[4096 + t * 2 + 1]);
    }
    __syncthreads();

    const int p = t >> 2, cp = t & 3;
    const int f = (p < 16) ? p : (p + 224);           // high block: f = p-32 mod 256
    const float sg = (p & 1) ? -1.0f : 1.0f;          // parity of f == parity of p
    const u64 sg2 = pack2(sg, sg);
    const u64x2 t0 = *(const u64x2*)&sT0[cp];
    const u64x2 t1 = *(const u64x2*)&sT128[cp];
    u64 aRe = ffma2(t1.x, sg2, t0.x);
    u64 aIm = ffma2(t1.y, sg2, t0.y);
    int m = f & 255;
#pragma unroll 4
    for (int h = 1; h < 128; h++) {
        const u64x2 A  = *(const u64x2*)&sA[(h << 2) + cp];
        const u64x2 Bv = *(const u64x2*)&sB[(h << 2) + cp];
        const u64x2 tv = *(const u64x2*)&stab[m];
        m = (m + f) & 255;
        aRe = ffma2(A.x, tv.x, aRe);  aRe = ffma2(A.y, tv.y, aRe);
        aIm = ffma2(Bv.x, tv.x, aIm); aIm = ffma2(Bv.y, tv.y, aIm);
    }
    const int c = ch * 8 + cp * 2;
    const size_t ix = (size_t)(p * 16 + kx) * 256 + b * 32 + c;
    *(float2*)&g_Xre[ix] = unpack2(aRe);
    *(float2*)&g_Xim[ix] = unpack2(aIm);
}

// ---------------------------------------------------------------------------
// K3: channel mixing with coalesced (transposed) weights.
// grid (16 kx, 32 p), 256 threads (one (b,co) each).
// ---------------------------------------------------------------------------
__global__ __launch_bounds__(256) void k3_mix() {
    __shared__ float sXr[256], sXi[256];
    __shared__ float swr[1024], swi[1024];
    const int t = threadIdx.x;
    const int kx = blockIdx.x, p = blockIdx.y;

    sXr[t] = g_Xre[(size_t)(p * 16 + kx) * 256 + t];
    sXi[t] = g_Xim[(size_t)(p * 16 + kx) * 256 + t];
    const int blk = p >> 4, m1 = p & 15;
    const int base = ((blk * 16 + m1) * 16 + kx) * 1024;
    for (int i = t; i < 1024; i += 256) {
        swr[i] = g_wtr[base + i];
        swi[i] = g_wti[base + i];
    }
    __syncthreads();

    const int b = t >> 5, co = t & 31;
    float accR = 0.f, accI = 0.f;
#pragma unroll
    for (int ci = 0; ci < 32; ci++) {
        const float Xr = sXr[b * 32 + ci], Xi = sXi[b * 32 + ci];
        const float Wr = swr[ci * 32 + co], Wi = swi[ci * 32 + co];
        accR += Xr * Wr - Xi * Wi;
        accI += Xr * Wi + Xi * Wr;
    }
    g_Yre[(size_t)(p * 16 + kx) * 256 + t] = accR;
    g_Yim[(size_t)(p * 16 + kx) * 256 + t] = accI;
}

// ---------------------------------------------------------------------------
// K4: inverse DFT over h. grid (8 hc, 8 = kxc4*cc2, 8 b) = 512 blocks,
// 256 threads: thread = hl(32) x copair(8); 4 kx per thread.
// ---------------------------------------------------------------------------
__global__ __launch_bounds__(256) void k4_idft_h() {
    __shared__ __align__(16) float4 sYA[1024];   // [(p*4+kxl)*8+cp] {Yr0,Yr1,Yi0,Yi1}
    __shared__ __align__(8)  float2 sYN[1024];   // {-Yi0,-Yi1}
    __shared__ __align__(16) float4 stab[256];
    const int t = threadIdx.x;
    const int hc = blockIdx.x;
    const int kxc = blockIdx.y >> 1, cc = blockIdx.y & 1;
    const int b = blockIdx.z;
    const int kx0 = kxc * 4;

    stab[t] = g_tab4[t];
    for (int i = t; i < 1024; i += 256) {
        const int p = i >> 5, kxl = (i >> 3) & 3, cp = i & 7;
        const size_t src = (size_t)(p * 16 + kx0 + kxl) * 256 + b * 32 + cc * 16 + cp * 2;
        const float2 yr = *(const float2*)&g_Yre[src];
        const float2 yi = *(const float2*)&g_Yim[src];
        sYA[i] = make_float4(yr.x, yr.y, yi.x, yi.y);
        sYN[i] = make_float2(-yi.x, -yi.y);
    }
    __syncthreads();

    const int hl = t >> 3, cp = t & 7;
    const int h = hc * 32 + hl;
    u64 Re[4], Im[4];
#pragma unroll
    for (int k = 0; k < 4; k++) { Re[k] = 0; Im[k] = 0; }

    int m = 0;                                   // p=0..15: f = p
#pragma unroll 1
    for (int p = 0; p < 16; p++) {
        const u64x2 tv = *(const u64x2*)&stab[m]; m = (m + h) & 255;
#pragma unroll
        for (int k = 0; k < 4; k++) {
            const u64x2 A = *(const u64x2*)&sYA[(p * 4 + k) * 8 + cp];
            const u64   N = *(const u64*)&sYN[(p * 4 + k) * 8 + cp];
            Re[k] = ffma2(A.x, tv.x, Re[k]); Re[k] = ffma2(N,   tv.y, Re[k]);
            Im[k] = ffma2(A.x, tv.y, Im[k]); Im[k] = ffma2(A.y, tv.x, Im[k]);
        }
    }
    m = (4096 - 16 * h) & 255;                   // p=16..31: f = p-32
#pragma unroll 1
    for (int p = 16; p < 32; p++) {
        const u64x2 tv = *(const u64x2*)&stab[m]; m = (m + h) & 255;
#pragma unroll
        for (int k = 0; k < 4; k++) {
            const u64x2 A = *(const u64x2*)&sYA[(p * 4 + k) * 8 + cp];
            const u64   N = *(const u64*)&sYN[(p * 4 + k) * 8 + cp];
            Re[k] = ffma2(A.x, tv.x, Re[k]); Re[k] = ffma2(N,   tv.y, Re[k]);
            Im[k] = ffma2(A.x, tv.y, Im[k]); Im[k] = ffma2(A.y, tv.x, Im[k]);
        }
    }

#pragma unroll
    for (int k = 0; k < 4; k++) {
        const int kx = kx0 + k;
        const float sc = (kx == 0 ? 1.0f : 2.0f) * (1.0f / 65536.0f);
        const u64 scl = pack2(sc, sc);
        const size_t dst = ((size_t)(b * 256 + h) * 16 + kx) * 32 + cc * 16 + cp * 2;
        *(float2*)&g_Gre[dst] = unpack2(fmul2(Re[k], scl));
        *(float2*)&g_Gim[dst] = unpack2(fmul2(Im[k], scl));
    }
}

// ---------------------------------------------------------------------------
// K5: inverse DFT over w, mirror quad: one (C,S) pair -> 4 outputs
// {w, w+128, 256-w, 128-w}. grid 2048 (b*256+h), 256 threads = co(32) x wg(8).
// ---------------------------------------------------------------------------
__device__ __forceinline__ void k5_body(const float4* stw, const u64* Gr, const u64* Gi,
                                        float* ob, int w, int co) {
    u64 C = 0, S = 0;
    const u64x2* tw = (const u64x2*)&stw[w * 16];
#pragma unroll
    for (int k = 0; k < 16; k++) {
        const u64x2 v = tw[k];
        C = ffma2(Gr[k], v.x, C);
        S = ffma2(Gi[k], v.y, S);
    }
    const float2 c2 = unpack2(C), s2 = unpack2(S);
    ob[w * 32 + co]                   = c2.x - s2.x;
    ob[(w + 128) * 32 + co]           = c2.y - s2.y;
    ob[(((256 - w) & 255)) * 32 + co] = c2.x + s2.x;
    ob[(128 - w) * 32 + co]           = c2.y + s2.y;
}

__global__ __launch_bounds__(256) void k5_idft_w(float* __restrict__ out) {
    __shared__ __align__(16) float4 stw[65 * 16];   // [w][k] (c, sg*c, s, sg*s)
    const int t = threadIdx.x;
    const int blk = blockIdx.x;                     // b*256 + h

    for (int i = t; i < 1040; i += 256) {
        const int w = i >> 4, k = i & 15;
        const float2 cs = g_tab2[(k * w) & 255];
        const float sgn = (k & 1) ? -1.0f : 1.0f;
        stw[i] = make_float4(cs.x, sgn * cs.x, cs.y, sgn * cs.y);
    }
    const int co = t & 31, wg = t >> 5;
    u64 Gr[16], Gi[16];
    {
        const float* pr = g_Gre + (size_t)blk * 512 + co;
        const float* pi = g_Gim + (size_t)blk * 512 + co;
#pragma unroll
        for (int k = 0; k < 16; k++) {
            const float r = pr[k * 32]; Gr[k] = pack2(r, r);
            const float u = pi[k * 32]; Gi[k] = pack2(u, u);
        }
    }
    __syncthreads();

    float* ob = out + (size_t)blk * 8192;
#pragma unroll 1
    for (int j = 0; j < 8; j++) k5_body(stw, Gr, Gi, ob, wg + 8 * j, co);
    if (wg == 0) k5_body(stw, Gr, Gi, ob, 64, co);
}

// ---------------------------------------------------------------------------
extern "C" void kernel_launch(void* const* d_in, const int* in_sizes, int n_in,
                              void* d_out, int out_size) {
    (void)n_in; (void)out_size; (void)in_sizes;
    const float* x  = (const float*)d_in[0];
    const float* wr = (const float*)d_in[1];
    const float* wi = (const float*)d_in[2];
    float* out = (float*)d_out;

    kA<<<4609, 128>>>(x, wr, wi);
    k2_dft_h<<<dim3(16, 4, 8), 128>>>();
    k3_mix<<<dim3(16, 32), 256>>>();
    k4_idft_h<<<dim3(8, 8, 8), 256>>>();
    k5_idft_w<<<2048, 256>>>(out);
}

// round 6
// speedup vs baseline: 1.1109x; 1.1109x over previous
#include <cuda_runtime.h>
#include <math.h>

// FNO spectral conv: truncated separable DFTs + mirror symmetries.
// B=8, H=W=256, CIN=COUT=32, M1=M2=16.
typedef unsigned long long u64;
typedef ulonglong2 u64x2;

// Tables / transposed weights / scratch (device globals).
__device__ __align__(16) float4 g_tab4[256];    // (cos, cos, sin, sin)
__device__ __align__(8)  float2 g_tab2[256];    // (cos, sin)
__device__ __align__(16) float  g_wtr[524288];  // [blk][m1][kx][ci][co]
__device__ __align__(16) float  g_wti[524288];
__device__ __align__(16) float  g_Tre[1048576]; // [b][kx][h][c]
__device__ __align__(16) float  g_Tim[1048576];
__device__ __align__(16) float  g_Xre[131072];  // [p*16+kx][b*32+c]
__device__ __align__(16) float  g_Xim[131072];
__device__ __align__(16) float  g_Yre[131072];  // [p*16+kx][b*32+co]
__device__ __align__(16) float  g_Yim[131072];
__device__ __align__(16) float  g_Gre[1048576]; // [b][h][kx][co]
__device__ __align__(16) float  g_Gim[1048576];

__device__ __forceinline__ u64 pack2(float lo, float hi) {
    u64 r; asm("mov.b64 %0,{%1,%2};" : "=l"(r) : "f"(lo), "f"(hi)); return r;
}
__device__ __forceinline__ float2 unpack2(u64 v) {
    float2 f; asm("mov.b64 {%0,%1},%2;" : "=f"(f.x), "=f"(f.y) : "l"(v)); return f;
}
__device__ __forceinline__ u64 ffma2(u64 a, u64 b, u64 c) {
    u64 d; asm("fma.rn.f32x2 %0,%1,%2,%3;" : "=l"(d) : "l"(a), "l"(b), "l"(c)); return d;
}
__device__ __forceinline__ u64 fmul2(u64 a, u64 b) {
    u64 d; asm("mul.rn.f32x2 %0,%1,%2;" : "=l"(d) : "l"(a), "l"(b)); return d;
}
__device__ __forceinline__ u64 fadd2(u64 a, u64 b) {
    u64 d; asm("add.rn.f32x2 %0,%1,%2;" : "=l"(d) : "l"(a), "l"(b)); return d;
}

// ---------------------------------------------------------------------------
// KA: fused launch, 128 threads.
//   blocks [0,2048):    forward w-DFT, one (b,h) row, all 32 channels.
//   blocks [2048,2560): tiled weight transpose -> [blk][m1][kx][ci][co].
//   block  2560:        twiddle tables.
// ---------------------------------------------------------------------------
__global__ __launch_bounds__(128) void kA(const float* __restrict__ x,
                                          const float* __restrict__ wr,
                                          const float* __restrict__ wi) {
    const int bid = blockIdx.x, t = threadIdx.x;

    if (bid < 2048) {
        // ---- forward DFT over w, real-input mirror symmetry ----
        __shared__ __align__(16) float4 se[128 * 8], so[128 * 8];
        __shared__ __align__(16) float4 stab[256];
        __shared__ __align__(16) float4 sx0[8], sx128[8];
        const float4* xb = (const float4*)(x + (size_t)bid * 8192);

        for (int i = t; i < 256; i += 128) {
            float s, c; sincospif((float)i * (1.0f / 128.0f), &s, &c);
            stab[i] = make_float4(c, c, s, s);
        }
        for (int i = t; i < 1016; i += 128) {
            const int w = 1 + (i >> 3), cq = i & 7;
            const float4 a = xb[w * 8 + cq];
            const float4 bb = xb[(256 - w) * 8 + cq];
            se[w * 8 + cq] = make_float4(a.x + bb.x, a.y + bb.y, a.z + bb.z, a.w + bb.w);
            so[w * 8 + cq] = make_float4(a.x - bb.x, a.y - bb.y, a.z - bb.z, a.w - bb.w);
        }
        if (t < 8) { sx0[t] = xb[t]; sx128[t] = xb[1024 + t]; }
        __syncthreads();

        const int kx = t >> 3, cq = t & 7;
        const float sg = (kx & 1) ? -1.0f : 1.0f;
        const u64 sg2 = pack2(sg, sg);
        const u64x2 e0 = *(const u64x2*)&sx0[cq];
        const u64x2 e1 = *(const u64x2*)&sx128[cq];
        u64 re0 = ffma2(e1.x, sg2, e0.x);
        u64 re1 = ffma2(e1.y, sg2, e0.y);
        u64 im0 = 0, im1 = 0;
        int m = kx;
#pragma unroll 4
        for (int w = 1; w < 128; w++) {
            const u64x2 ev = *(const u64x2*)&se[w * 8 + cq];
            const u64x2 ov = *(const u64x2*)&so[w * 8 + cq];
            const u64x2 tv = *(const u64x2*)&stab[m];
            m = (m + kx) & 255;
            re0 = ffma2(ev.x, tv.x, re0); re1 = ffma2(ev.y, tv.x, re1);
            im0 = ffma2(ov.x, tv.y, im0); im1 = ffma2(ov.y, tv.y, im1);
        }
        const int b = bid >> 8, h = bid & 255;
        const size_t o4 = ((size_t)((b * 16 + kx) * 256 + h)) * 8 + cq;
        const float2 r0 = unpack2(re0), r1 = unpack2(re1);
        ((float4*)g_Tre)[o4] = make_float4(r0.x, r0.y, r1.x, r1.y);
        const u64 n1 = pack2(-1.0f, -1.0f);
        const float2 i0 = unpack2(fmul2(im0, n1)), i1 = unpack2(fmul2(im1, n1));
        ((float4*)g_Tim)[o4] = make_float4(i0.x, i0.y, i1.x, i1.y);

    } else if (bid < 2560) {
        // ---- tiled transpose: [ci*32+co][m1*16+kx] -> [m1*16+kx][ci*32+co] ----
        __shared__ float sw[32][33], sv[32][33];
        const int tt = bid - 2048;
        const int blkw = tt >> 8, tile = tt & 255;
        const int tr = tile >> 3, tc = tile & 7;   // row tile (1024/32), col tile (256/32)
        const int rr = t >> 5, c = t & 31;
        const float* srcR = wr + blkw * 262144;
        const float* srcI = wi + blkw * 262144;
#pragma unroll
        for (int ph = 0; ph < 8; ph++) {
            const int rl = ph * 4 + rr;
            const int row = tr * 32 + rl, col = tc * 32 + c;
            sw[rl][c] = srcR[row * 256 + col];
            sv[rl][c] = srcI[row * 256 + col];
        }
        __syncthreads();
        float* dR = g_wtr + blkw * 262144;
        float* dI = g_wti + blkw * 262144;
#pragma unroll
        for (int ph = 0; ph < 8; ph++) {
            const int cl = ph * 4 + rr;
            const int dcol = tc * 32 + cl, drow = tr * 32 + c;
            dR[dcol * 1024 + drow] = sw[c][cl];
            dI[dcol * 1024 + drow] = sv[c][cl];
        }
    } else {
        for (int i = t; i < 256; i += 128) {
            float s, c; sincospif((float)i * (1.0f / 128.0f), &s, &c);
            g_tab4[i] = make_float4(c, c, s, s);
            g_tab2[i] = make_float2(c, s);
        }
    }
}

// ---------------------------------------------------------------------------
// K2: forward DFT over h (32 kept modes), complex mirror symmetry.
// f = p (p<16) or p+224 (= p-32 mod 256). 4 independent accumulator chains.
// grid (16 kx, 4 ch, 8 b) = 512 blocks, 128 threads: p(32) x cpair(4).
// ---------------------------------------------------------------------------
__global__ __launch_bounds__(128) void k2_dft_h() {
    __shared__ __align__(16) float4 sA[128 * 4];   // {Er0,Er1,Oi0,Oi1}
    __shared__ __align__(16) float4 sB[128 * 4];   // {Ei0,Ei1,-Or0,-Or1}
    __shared__ __align__(16) float4 stab[256];
    __shared__ __align__(16) float4 sT0[4], sT128[4];
    const int t = threadIdx.x;
    const int kx = blockIdx.x, ch = blockIdx.y, b = blockIdx.z;
    const float* srcR = g_Tre + ((size_t)(b * 16 + kx) * 256) * 32 + ch * 8;
    const float* srcI = g_Tim + ((size_t)(b * 16 + kx) * 256) * 32 + ch * 8;

    for (int i = t; i < 256; i += 128) stab[i] = g_tab4[i];
    for (int i = t; i < 508; i += 128) {
        const int h = 1 + (i >> 2), cp = i & 3;
        const float2 ar = *(const float2*)&srcR[h * 32 + cp * 2];
        const float2 br = *(const float2*)&srcR[(256 - h) * 32 + cp * 2];
        const float2 ai = *(const float2*)&srcI[h * 32 + cp * 2];
        const float2 bi = *(const float2*)&srcI[(256 - h) * 32 + cp * 2];
        sA[(h << 2) + cp] = make_float4(ar.x + br.x, ar.y + br.y, ai.x - bi.x, ai.y - bi.y);
        sB[(h << 2) + cp] = make_float4(ai.x + bi.x, ai.y + bi.y, br.x - ar.x, br.y - ar.y);
    }
    if (t < 4) {
        sT0[t]   = make_float4(srcR[t * 2], srcR[t * 2 + 1], srcI[t * 2], srcI[t * 2 + 1]);
        sT128[t] = make_float4(srcR[4096 + t * 2], srcR[4096 + t * 2 + 1],
                               srcI[4096 + t * 2], srcI[4096 + t * 2 + 1]);
    }
    __syncthreads();

    const int p = t >> 2, cp = t & 3;
    const int f = (p < 16) ? p : (p + 224);           // high block: f = p-32 mod 256
    const float sg = (p & 1) ? -1.0f : 1.0f;          // parity of f == parity of p
    const u64 sg2 = pack2(sg, sg);
    const u64x2 t0 = *(const u64x2*)&sT0[cp];
    const u64x2 t1 = *(const u64x2*)&sT128[cp];
    u64 aRe1 = ffma2(t1.x, sg2, t0.x), aRe2 = 0;
    u64 aIm1 = ffma2(t1.y, sg2, t0.y), aIm2 = 0;
    int m = f & 255;
#pragma unroll 4
    for (int h = 1; h < 128; h++) {
        const u64x2 A  = *(const u64x2*)&sA[(h << 2) + cp];
        const u64x2 Bv = *(const u64x2*)&sB[(h << 2) + cp];
        const u64x2 tv = *(const u64x2*)&stab[m];
        m = (m + f) & 255;
        aRe1 = ffma2(A.x, tv.x, aRe1);  aRe2 = ffma2(A.y, tv.y, aRe2);
        aIm1 = ffma2(Bv.x, tv.x, aIm1); aIm2 = ffma2(Bv.y, tv.y, aIm2);
    }
    const int c = ch * 8 + cp * 2;
    const size_t ix = (size_t)(p * 16 + kx) * 256 + b * 32 + c;
    *(float2*)&g_Xre[ix] = unpack2(fadd2(aRe1, aRe2));
    *(float2*)&g_Xim[ix] = unpack2(fadd2(aIm1, aIm2));
}

// ---------------------------------------------------------------------------
// K3: channel mixing with coalesced (transposed) weights.
// grid (16 kx, 32 p), 256 threads (one (b,co) each).
// ---------------------------------------------------------------------------
__global__ __launch_bounds__(256) void k3_mix() {
    __shared__ float sXr[256], sXi[256];
    __shared__ float swr[1024], swi[1024];
    const int t = threadIdx.x;
    const int kx = blockIdx.x, p = blockIdx.y;

    sXr[t] = g_Xre[(size_t)(p * 16 + kx) * 256 + t];
    sXi[t] = g_Xim[(size_t)(p * 16 + kx) * 256 + t];
    const int blk = p >> 4, m1 = p & 15;
    const int base = ((blk * 16 + m1) * 16 + kx) * 1024;
    for (int i = t; i < 1024; i += 256) {
        swr[i] = g_wtr[base + i];
        swi[i] = g_wti[base + i];
    }
    __syncthreads();

    const int b = t >> 5, co = t & 31;
    float accR = 0.f, accI = 0.f;
#pragma unroll
    for (int ci = 0; ci < 32; ci++) {
        const float Xr = sXr[b * 32 + ci], Xi = sXi[b * 32 + ci];
        const float Wr = swr[ci * 32 + co], Wi = swi[ci * 32 + co];
        accR += Xr * Wr - Xi * Wi;
        accI += Xr * Wi + Xi * Wr;
    }
    g_Yre[(size_t)(p * 16 + kx) * 256 + t] = accR;
    g_Yim[(size_t)(p * 16 + kx) * 256 + t] = accI;
}

// ---------------------------------------------------------------------------
// K4: inverse DFT over h. grid (8 hc, 8 = kxc4*cc2, 8 b) = 512 blocks,
// 256 threads: thread = hl(32) x copair(8); 4 kx per thread.
// 16 independent accumulator chains, single LDS.128 per (p,k), no sYN.
// ---------------------------------------------------------------------------
__global__ __launch_bounds__(256) void k4_idft_h() {
    __shared__ __align__(16) float4 sYA[1024];   // [(p*4+kxl)*8+cp] {Yr0,Yr1,Yi0,Yi1}
    __shared__ __align__(16) float4 stab[256];
    const int t = threadIdx.x;
    const int hc = blockIdx.x;
    const int kxc = blockIdx.y >> 1, cc = blockIdx.y & 1;
    const int b = blockIdx.z;
    const int kx0 = kxc * 4;

    stab[t] = g_tab4[t];
    for (int i = t; i < 1024; i += 256) {
        const int p = i >> 5, kxl = (i >> 3) & 3, cp = i & 7;
        const size_t src = (size_t)(p * 16 + kx0 + kxl) * 256 + b * 32 + cc * 16 + cp * 2;
        const float2 yr = *(const float2*)&g_Yre[src];
        const float2 yi = *(const float2*)&g_Yim[src];
        sYA[i] = make_float4(yr.x, yr.y, yi.x, yi.y);
    }
    __syncthreads();

    const int hl = t >> 3, cp = t & 7;
    const int h = hc * 32 + hl;
    u64 Rc[4], Rs[4], Is[4], Ic[4];
#pragma unroll
    for (int k = 0; k < 4; k++) { Rc[k] = 0; Rs[k] = 0; Is[k] = 0; Ic[k] = 0; }

    int m = 0;                                   // p=0..15: f = p
#pragma unroll 1
    for (int p = 0; p < 16; p++) {
        const u64x2 tv = *(const u64x2*)&stab[m]; m = (m + h) & 255;
#pragma unroll
        for (int k = 0; k < 4; k++) {
            const u64x2 A = *(const u64x2*)&sYA[(p * 4 + k) * 8 + cp];
            Rc[k] = ffma2(A.x, tv.x, Rc[k]); Rs[k] = ffma2(A.y, tv.y, Rs[k]);
            Is[k] = ffma2(A.x, tv.y, Is[k]); Ic[k] = ffma2(A.y, tv.x, Ic[k]);
        }
    }
    m = (4096 - 16 * h) & 255;                   // p=16..31: f = p-32
#pragma unroll 1
    for (int p = 16; p < 32; p++) {
        const u64x2 tv = *(const u64x2*)&stab[m]; m = (m + h) & 255;
#pragma unroll
        for (int k = 0; k < 4; k++) {
            const u64x2 A = *(const u64x2*)&sYA[(p * 4 + k) * 8 + cp];
            Rc[k] = ffma2(A.x, tv.x, Rc[k]); Rs[k] = ffma2(A.y, tv.y, Rs[k]);
            Is[k] = ffma2(A.x, tv.y, Is[k]); Ic[k] = ffma2(A.y, tv.x, Ic[k]);
        }
    }

    const u64 n1 = pack2(-1.0f, -1.0f);
#pragma unroll
    for (int k = 0; k < 4; k++) {
        const int kx = kx0 + k;
        const float sc = (kx == 0 ? 1.0f : 2.0f) * (1.0f / 65536.0f);
        const u64 scl = pack2(sc, sc);
        const u64 Re = ffma2(Rs[k], n1, Rc[k]);     // Rc - Rs
        const u64 Im = fadd2(Is[k], Ic[k]);
        const size_t dst = ((size_t)(b * 256 + h) * 16 + kx) * 32 + cc * 16 + cp * 2;
        *(float2*)&g_Gre[dst] = unpack2(fmul2(Re, scl));
        *(float2*)&g_Gim[dst] = unpack2(fmul2(Im, scl));
    }
}

// ---------------------------------------------------------------------------
// K5: inverse DFT over w, mirror quad: one (C,S) pair -> 4 outputs
// {w, w+128, 256-w, 128-w}. grid 2048 (b*256+h), 256 threads = co(32) x wg(8).
// ---------------------------------------------------------------------------
__device__ __forceinline__ void k5_body(const float4* stw, const u64* Gr, const u64* Gi,
                                        float* ob, int w, int co) {
    u64 C = 0, S = 0;
    const u64x2* tw = (const u64x2*)&stw[w * 16];
#pragma unroll
    for (int k = 0; k < 16; k++) {
        const u64x2 v = tw[k];
        C = ffma2(Gr[k], v.x, C);
        S = ffma2(Gi[k], v.y, S);
    }
    const float2 c2 = unpack2(C), s2 = unpack2(S);
    ob[w * 32 + co]                   = c2.x - s2.x;
    ob[(w + 128) * 32 + co]           = c2.y - s2.y;
    ob[(((256 - w) & 255)) * 32 + co] = c2.x + s2.x;
    ob[(128 - w) * 32 + co]           = c2.y + s2.y;
}

__global__ __launch_bounds__(256) void k5_idft_w(float* __restrict__ out) {
    __shared__ __align__(16) float4 stw[65 * 16];   // [w][k] (c, sg*c, s, sg*s)
    const int t = threadIdx.x;
    const int blk = blockIdx.x;                     // b*256 + h

    for (int i = t; i < 1040; i += 256) {
        const int w = i >> 4, k = i & 15;
        const float2 cs = g_tab2[(k * w) & 255];
        const float sgn = (k & 1) ? -1.0f : 1.0f;
        stw[i] = make_float4(cs.x, sgn * cs.x, cs.y, sgn * cs.y);
    }
    const int co = t & 31, wg = t >> 5;
    u64 Gr[16], Gi[16];
    {
        const float* pr = g_Gre + (size_t)blk * 512 + co;
        const float* pi = g_Gim + (size_t)blk * 512 + co;
#pragma unroll
        for (int k = 0; k < 16; k++) {
            const float r = pr[k * 32]; Gr[k] = pack2(r, r);
            const float u = pi[k * 32]; Gi[k] = pack2(u, u);
        }
    }
    __syncthreads();

    float* ob = out + (size_t)blk * 8192;
#pragma unroll 1
    for (int j = 0; j < 8; j++) k5_body(stw, Gr, Gi, ob, wg + 8 * j, co);
    if (wg == 0) k5_body(stw, Gr, Gi, ob, 64, co);
}

// ---------------------------------------------------------------------------
extern "C" void kernel_launch(void* const* d_in, const int* in_sizes, int n_in,
                              void* d_out, int out_size) {
    (void)n_in; (void)out_size; (void)in_sizes;
    const float* x  = (const float*)d_in[0];
    const float* wr = (const float*)d_in[1];
    const float* wi = (const float*)d_in[2];
    float* out = (float*)d_out;

    kA<<<2561, 128>>>(x, wr, wi);
    k2_dft_h<<<dim3(16, 4, 8), 128>>>();
    k3_mix<<<dim3(16, 32), 256>>>();
    k4_idft_h<<<dim3(8, 8, 8), 256>>>();
    k5_idft_w<<<2048, 256>>>(out);
}

// round 7
// speedup vs baseline: 1.1943x; 1.0751x over previous
#include <cuda_runtime.h>
#include <math.h>

// FNO spectral conv: truncated separable DFTs + mirror/conjugate symmetries.
// B=8, H=W=256, CIN=COUT=32, M1=M2=16.
typedef unsigned long long u64;
typedef ulonglong2 u64x2;

// Tables / transposed weights / scratch (device globals).
__device__ __align__(16) float4 g_tab4[256];    // (cos, cos, sin, sin)
__device__ __align__(8)  float2 g_tab2[256];    // (cos, sin)
__device__ __align__(16) float  g_wtr[524288];  // [blk][m1][kx][ci][co]
__device__ __align__(16) float  g_wti[524288];
__device__ __align__(16) float  g_Tre[1048576]; // [b][kx][h][c]
__device__ __align__(16) float  g_Tim[1048576];
__device__ __align__(16) float  g_Xre[131072];  // [p*16+kx][b*32+c]
__device__ __align__(16) float  g_Xim[131072];
__device__ __align__(16) float  g_Yre[131072];  // [p*16+kx][b*32+co]
__device__ __align__(16) float  g_Yim[131072];
__device__ __align__(16) float  g_Gre[1048576]; // [b][h][kx][co]
__device__ __align__(16) float  g_Gim[1048576];

__device__ __forceinline__ u64 pack2(float lo, float hi) {
    u64 r; asm("mov.b64 %0,{%1,%2};" : "=l"(r) : "f"(lo), "f"(hi)); return r;
}
__device__ __forceinline__ float2 unpack2(u64 v) {
    float2 f; asm("mov.b64 {%0,%1},%2;" : "=f"(f.x), "=f"(f.y) : "l"(v)); return f;
}
__device__ __forceinline__ u64 ffma2(u64 a, u64 b, u64 c) {
    u64 d; asm("fma.rn.f32x2 %0,%1,%2,%3;" : "=l"(d) : "l"(a), "l"(b), "l"(c)); return d;
}
__device__ __forceinline__ u64 fmul2(u64 a, u64 b) {
    u64 d; asm("mul.rn.f32x2 %0,%1,%2;" : "=l"(d) : "l"(a), "l"(b)); return d;
}
__device__ __forceinline__ u64 fadd2(u64 a, u64 b) {
    u64 d; asm("add.rn.f32x2 %0,%1,%2;" : "=l"(d) : "l"(a), "l"(b)); return d;
}
__device__ __forceinline__ u64 fsub2(u64 a, u64 b) {
    u64 d; asm("sub.rn.f32x2 %0,%1,%2;" : "=l"(d) : "l"(a), "l"(b)); return d;
}

// ---------------------------------------------------------------------------
// KA: fused launch, 128 threads.
//   blocks [0,2048):    forward w-DFT, one (b,h) row, all 32 channels.
//   blocks [2048,2560): tiled weight transpose -> [blk][m1][kx][ci][co].
//   block  2560:        twiddle tables.
// ---------------------------------------------------------------------------
__global__ __launch_bounds__(128) void kA(const float* __restrict__ x,
                                          const float* __restrict__ wr,
                                          const float* __restrict__ wi) {
    const int bid = blockIdx.x, t = threadIdx.x;

    if (bid < 2048) {
        // ---- forward DFT over w, real-input mirror symmetry ----
        __shared__ __align__(16) float4 se[128 * 8], so[128 * 8];
        __shared__ __align__(16) float4 stab[256];
        __shared__ __align__(16) float4 sx0[8], sx128[8];
        const float4* xb = (const float4*)(x + (size_t)bid * 8192);

        for (int i = t; i < 256; i += 128) {
            float s, c; sincospif((float)i * (1.0f / 128.0f), &s, &c);
            stab[i] = make_float4(c, c, s, s);
        }
        for (int i = t; i < 1016; i += 128) {
            const int w = 1 + (i >> 3), cq = i & 7;
            const float4 a = xb[w * 8 + cq];
            const float4 bb = xb[(256 - w) * 8 + cq];
            se[w * 8 + cq] = make_float4(a.x + bb.x, a.y + bb.y, a.z + bb.z, a.w + bb.w);
            so[w * 8 + cq] = make_float4(a.x - bb.x, a.y - bb.y, a.z - bb.z, a.w - bb.w);
        }
        if (t < 8) { sx0[t] = xb[t]; sx128[t] = xb[1024 + t]; }
        __syncthreads();

        const int kx = t >> 3, cq = t & 7;
        const float sg = (kx & 1) ? -1.0f : 1.0f;
        const u64 sg2 = pack2(sg, sg);
        const u64x2 e0 = *(const u64x2*)&sx0[cq];
        const u64x2 e1 = *(const u64x2*)&sx128[cq];
        u64 re0 = ffma2(e1.x, sg2, e0.x);
        u64 re1 = ffma2(e1.y, sg2, e0.y);
        u64 im0 = 0, im1 = 0;
        int m = kx;
#pragma unroll 4
        for (int w = 1; w < 128; w++) {
            const u64x2 ev = *(const u64x2*)&se[w * 8 + cq];
            const u64x2 ov = *(const u64x2*)&so[w * 8 + cq];
            const u64x2 tv = *(const u64x2*)&stab[m];
            m = (m + kx) & 255;
            re0 = ffma2(ev.x, tv.x, re0); re1 = ffma2(ev.y, tv.x, re1);
            im0 = ffma2(ov.x, tv.y, im0); im1 = ffma2(ov.y, tv.y, im1);
        }
        const int b = bid >> 8, h = bid & 255;
        const size_t o4 = ((size_t)((b * 16 + kx) * 256 + h)) * 8 + cq;
        const float2 r0 = unpack2(re0), r1 = unpack2(re1);
        ((float4*)g_Tre)[o4] = make_float4(r0.x, r0.y, r1.x, r1.y);
        const u64 n1 = pack2(-1.0f, -1.0f);
        const float2 i0 = unpack2(fmul2(im0, n1)), i1 = unpack2(fmul2(im1, n1));
        ((float4*)g_Tim)[o4] = make_float4(i0.x, i0.y, i1.x, i1.y);

    } else if (bid < 2560) {
        // ---- tiled transpose: [ci*32+co][m1*16+kx] -> [m1*16+kx][ci*32+co] ----
        __shared__ float sw[32][33], sv[32][33];
        const int tt = bid - 2048;
        const int blkw = tt >> 8, tile = tt & 255;
        const int tr = tile >> 3, tc = tile & 7;
        const int rr = t >> 5, c = t & 31;
        const float* srcR = wr + blkw * 262144;
        const float* srcI = wi + blkw * 262144;
#pragma unroll
        for (int ph = 0; ph < 8; ph++) {
            const int rl = ph * 4 + rr;
            const int row = tr * 32 + rl, col = tc * 32 + c;
            sw[rl][c] = srcR[row * 256 + col];
            sv[rl][c] = srcI[row * 256 + col];
        }
        __syncthreads();
        float* dR = g_wtr + blkw * 262144;
        float* dI = g_wti + blkw * 262144;
#pragma unroll
        for (int ph = 0; ph < 8; ph++) {
            const int cl = ph * 4 + rr;
            const int dcol = tc * 32 + cl, drow = tr * 32 + c;
            dR[dcol * 1024 + drow] = sw[c][cl];
            dI[dcol * 1024 + drow] = sv[c][cl];
        }
    } else {
        for (int i = t; i < 256; i += 128) {
            float s, c; sincospif((float)i * (1.0f / 128.0f), &s, &c);
            g_tab4[i] = make_float4(c, c, s, s);
            g_tab2[i] = make_float2(c, s);
        }
    }
}

// ---------------------------------------------------------------------------
// K2: forward DFT over h, conjugate-pair generators.
// Generator f = p (p = 0..16). Chains C1=ΣEr c, C2=ΣOi s, C3=ΣEi c, C4=Σ(-Or) s.
// X(+p) = (C1+C2, C3+C4) -> row p (p<16); X(-p) = (C1-C2, C3-C4) -> row 32-p (p>=1).
// grid (16 kx, 2 ch, 8 b) = 256 blocks, 136 threads: slot p = t>>3 (0..16), cp = t&7.
// ---------------------------------------------------------------------------
__global__ __launch_bounds__(136) void k2_dft_h() {
    __shared__ __align__(16) float4 sA[128 * 8];   // {Er0,Er1,Oi0,Oi1}
    __shared__ __align__(16) float4 sB[128 * 8];   // {Ei0,Ei1,-Or0,-Or1}
    __shared__ __align__(16) float4 stab[256];
    __shared__ __align__(16) float4 sT0[8], sT128[8];
    const int t = threadIdx.x;
    const int kx = blockIdx.x, ch = blockIdx.y, b = blockIdx.z;
    const float* srcR = g_Tre + ((size_t)(b * 16 + kx) * 256) * 32 + ch * 16;
    const float* srcI = g_Tim + ((size_t)(b * 16 + kx) * 256) * 32 + ch * 16;

    for (int i = t; i < 256; i += 136) stab[i] = g_tab4[i];
    for (int i = t; i < 1016; i += 136) {
        const int h = 1 + (i >> 3), cp = i & 7;
        const float2 ar = *(const float2*)&srcR[h * 32 + cp * 2];
        const float2 br = *(const float2*)&srcR[(256 - h) * 32 + cp * 2];
        const float2 ai = *(const float2*)&srcI[h * 32 + cp * 2];
        const float2 bi = *(const float2*)&srcI[(256 - h) * 32 + cp * 2];
        sA[(h << 3) + cp] = make_float4(ar.x + br.x, ar.y + br.y, ai.x - bi.x, ai.y - bi.y);
        sB[(h << 3) + cp] = make_float4(ai.x + bi.x, ai.y + bi.y, br.x - ar.x, br.y - ar.y);
    }
    if (t < 8) {
        sT0[t]   = make_float4(srcR[t * 2], srcR[t * 2 + 1], srcI[t * 2], srcI[t * 2 + 1]);
        sT128[t] = make_float4(srcR[4096 + t * 2], srcR[4096 + t * 2 + 1],
                               srcI[4096 + t * 2], srcI[4096 + t * 2 + 1]);
    }
    __syncthreads();

    const int p = t >> 3, cp = t & 7;
    const float sg = (p & 1) ? -1.0f : 1.0f;       // boundary parity (same for +-p)
    const u64 sg2 = pack2(sg, sg);
    const u64x2 t0 = *(const u64x2*)&sT0[cp];
    const u64x2 t1 = *(const u64x2*)&sT128[cp];
    u64 C1 = ffma2(t1.x, sg2, t0.x), C2 = 0;       // boundary folded into C1/C3
    u64 C3 = ffma2(t1.y, sg2, t0.y), C4 = 0;
    int m = p;
#pragma unroll 4
    for (int h = 1; h < 128; h++) {
        const u64x2 A  = *(const u64x2*)&sA[(h << 3) + cp];
        const u64x2 Bv = *(const u64x2*)&sB[(h << 3) + cp];
        const u64x2 tv = *(const u64x2*)&stab[m];
        m = (m + p) & 255;
        C1 = ffma2(A.x, tv.x, C1);  C2 = ffma2(A.y, tv.y, C2);
        C3 = ffma2(Bv.x, tv.x, C3); C4 = ffma2(Bv.y, tv.y, C4);
    }
    const int c = ch * 16 + cp * 2;
    if (p < 16) {                                   // X(+p) -> row p
        const size_t ix = (size_t)(p * 16 + kx) * 256 + b * 32 + c;
        *(float2*)&g_Xre[ix] = unpack2(fadd2(C1, C2));
        *(float2*)&g_Xim[ix] = unpack2(fadd2(C3, C4));
    }
    if (p >= 1) {                                   // X(-p) -> row 32-p
        const size_t ix = (size_t)((32 - p) * 16 + kx) * 256 + b * 32 + c;
        *(float2*)&g_Xre[ix] = unpack2(fsub2(C1, C2));
        *(float2*)&g_Xim[ix] = unpack2(fsub2(C3, C4));
    }
}

// ---------------------------------------------------------------------------
// K3: channel mixing with coalesced (transposed) weights.
// grid (16 kx, 32 p), 256 threads (one (b,co) each).
// ---------------------------------------------------------------------------
__global__ __launch_bounds__(256) void k3_mix() {
    __shared__ float sXr[256], sXi[256];
    __shared__ float swr[1024], swi[1024];
    const int t = threadIdx.x;
    const int kx = blockIdx.x, p = blockIdx.y;

    sXr[t] = g_Xre[(size_t)(p * 16 + kx) * 256 + t];
    sXi[t] = g_Xim[(size_t)(p * 16 + kx) * 256 + t];
    const int blk = p >> 4, m1 = p & 15;
    const int base = ((blk * 16 + m1) * 16 + kx) * 1024;
    for (int i = t; i < 1024; i += 256) {
        swr[i] = g_wtr[base + i];
        swi[i] = g_wti[base + i];
    }
    __syncthreads();

    const int b = t >> 5, co = t & 31;
    float accR = 0.f, accI = 0.f;
#pragma unroll
    for (int ci = 0; ci < 32; ci++) {
        const float Xr = sXr[b * 32 + ci], Xi = sXi[b * 32 + ci];
        const float Wr = swr[ci * 32 + co], Wi = swi[ci * 32 + co];
        accR += Xr * Wr - Xi * Wi;
        accI += Xr * Wi + Xi * Wr;
    }
    g_Yre[(size_t)(p * 16 + kx) * 256 + t] = accR;
    g_Yim[(size_t)(p * 16 + kx) * 256 + t] = accI;
}

// ---------------------------------------------------------------------------
// K4: inverse DFT over h, conjugate-pair outputs.
// Chains Rc,Rs,Is,Ic give G(h) = (Rc-Rs, Is+Ic) AND G(256-h) = (Rc+Rs, Ic-Is).
// h = hc*32 + hl + 1 in 1..128 direct; mirror 129..255 (h<128); h==128 threads
// also emit the trivial h=0 row. grid (4 hc, 8 = kxc4*cc2, 8 b) = 256 blocks.
// ---------------------------------------------------------------------------
__global__ __launch_bounds__(256) void k4_idft_h() {
    __shared__ __align__(16) float4 sYA[1024];   // [(p*4+kxl)*8+cp] {Yr0,Yr1,Yi0,Yi1}
    __shared__ __align__(16) float4 stab[256];
    const int t = threadIdx.x;
    const int hc = blockIdx.x;
    const int kxc = blockIdx.y >> 1, cc = blockIdx.y & 1;
    const int b = blockIdx.z;
    const int kx0 = kxc * 4;

    stab[t] = g_tab4[t];
    for (int i = t; i < 1024; i += 256) {
        const int p = i >> 5, kxl = (i >> 3) & 3, cp = i & 7;
        const size_t src = (size_t)(p * 16 + kx0 + kxl) * 256 + b * 32 + cc * 16 + cp * 2;
        const float2 yr = *(const float2*)&g_Yre[src];
        const float2 yi = *(const float2*)&g_Yim[src];
        sYA[i] = make_float4(yr.x, yr.y, yi.x, yi.y);
    }
    __syncthreads();

    const int hl = t >> 3, cp = t & 7;
    const int h = hc * 32 + hl + 1;              // 1..128
    u64 Rc[4], Rs[4], Is[4], Ic[4];
#pragma unroll
    for (int k = 0; k < 4; k++) { Rc[k] = 0; Rs[k] = 0; Is[k] = 0; Ic[k] = 0; }

    int m = 0;                                   // p=0..15: f = p
#pragma unroll 1
    for (int p = 0; p < 16; p++) {
        const u64x2 tv = *(const u64x2*)&stab[m]; m = (m + h) & 255;
#pragma unroll
        for (int k = 0; k < 4; k++) {
            const u64x2 A = *(const u64x2*)&sYA[(p * 4 + k) * 8 + cp];
            Rc[k] = ffma2(A.x, tv.x, Rc[k]); Rs[k] = ffma2(A.y, tv.y, Rs[k]);
            Is[k] = ffma2(A.x, tv.y, Is[k]); Ic[k] = ffma2(A.y, tv.x, Ic[k]);
        }
    }
    m = (4096 - 16 * h) & 255;                   // p=16..31: f = p-32
#pragma unroll 1
    for (int p = 16; p < 32; p++) {
        const u64x2 tv = *(const u64x2*)&stab[m]; m = (m + h) & 255;
#pragma unroll
        for (int k = 0; k < 4; k++) {
            const u64x2 A = *(const u64x2*)&sYA[(p * 4 + k) * 8 + cp];
            Rc[k] = ffma2(A.x, tv.x, Rc[k]); Rs[k] = ffma2(A.y, tv.y, Rs[k]);
            Is[k] = ffma2(A.x, tv.y, Is[k]); Ic[k] = ffma2(A.y, tv.x, Ic[k]);
        }
    }

#pragma unroll
    for (int k = 0; k < 4; k++) {
        const int kx = kx0 + k;
        const float sc = (kx == 0 ? 1.0f : 2.0f) * (1.0f / 65536.0f);
        const u64 scl = pack2(sc, sc);
        const size_t rowbase = ((size_t)(b * 256) * 16 + kx) * 32 + cc * 16 + cp * 2;
        // direct: row h
        *(float2*)&g_Gre[rowbase + (size_t)h * 512] = unpack2(fmul2(fsub2(Rc[k], Rs[k]), scl));
        *(float2*)&g_Gim[rowbase + (size_t)h * 512] = unpack2(fmul2(fadd2(Is[k], Ic[k]), scl));
        // mirror: row 256-h (skip h==128, self-mirror)
        if (h < 128) {
            *(float2*)&g_Gre[rowbase + (size_t)(256 - h) * 512] =
                unpack2(fmul2(fadd2(Rc[k], Rs[k]), scl));
            *(float2*)&g_Gim[rowbase + (size_t)(256 - h) * 512] =
                unpack2(fmul2(fsub2(Ic[k], Is[k]), scl));
        }
    }

    if (h == 128) {                              // emit trivial h=0 row: G(0) = sum Y
        u64 Zr[4], Zi[4];
#pragma unroll
        for (int k = 0; k < 4; k++) { Zr[k] = 0; Zi[k] = 0; }
#pragma unroll 1
        for (int p = 0; p < 32; p++) {
#pragma unroll
            for (int k = 0; k < 4; k++) {
                const u64x2 A = *(const u64x2*)&sYA[(p * 4 + k) * 8 + cp];
                Zr[k] = fadd2(Zr[k], A.x);
                Zi[k] = fadd2(Zi[k], A.y);
            }
        }
#pragma unroll
        for (int k = 0; k < 4; k++) {
            const int kx = kx0 + k;
            const float sc = (kx == 0 ? 1.0f : 2.0f) * (1.0f / 65536.0f);
            const u64 scl = pack2(sc, sc);
            const size_t dst = ((size_t)(b * 256) * 16 + kx) * 32 + cc * 16 + cp * 2;
            *(float2*)&g_Gre[dst] = unpack2(fmul2(Zr[k], scl));
            *(float2*)&g_Gim[dst] = unpack2(fmul2(Zi[k], scl));
        }
    }
}

// ---------------------------------------------------------------------------
// K5: inverse DFT over w, mirror quad: one (C,S) pair -> 4 outputs
// {w, w+128, 256-w, 128-w}. grid 2048 (b*256+h), 256 threads = co(32) x wg(8).
// ---------------------------------------------------------------------------
__device__ __forceinline__ void k5_body(const float4* stw, const u64* Gr, const u64* Gi,
                                        float* ob, int w, int co) {
    u64 C = 0, S = 0;
    const u64x2* tw = (const u64x2*)&stw[w * 16];
#pragma unroll
    for (int k = 0; k < 16; k++) {
        const u64x2 v = tw[k];
        C = ffma2(Gr[k], v.x, C);
        S = ffma2(Gi[k], v.y, S);
    }
    const float2 c2 = unpack2(C), s2 = unpack2(S);
    ob[w * 32 + co]                   = c2.x - s2.x;
    ob[(w + 128) * 32 + co]           = c2.y - s2.y;
    ob[(((256 - w) & 255)) * 32 + co] = c2.x + s2.x;
    ob[(128 - w) * 32 + co]           = c2.y + s2.y;
}

__global__ __launch_bounds__(256) void k5_idft_w(float* __restrict__ out) {
    __shared__ __align__(16) float4 stw[65 * 16];   // [w][k] (c, sg*c, s, sg*s)
    const int t = threadIdx.x;
    const int blk = blockIdx.x;                     // b*256 + h

    for (int i = t; i < 1040; i += 256) {
        const int w = i >> 4, k = i & 15;
        const float2 cs = g_tab2[(k * w) & 255];
        const float sgn = (k & 1) ? -1.0f : 1.0f;
        stw[i] = make_float4(cs.x, sgn * cs.x, cs.y, sgn * cs.y);
    }
    const int co = t & 31, wg = t >> 5;
    u64 Gr[16], Gi[16];
    {
        const float* pr = g_Gre + (size_t)blk * 512 + co;
        const float* pi = g_Gim + (size_t)blk * 512 + co;
#pragma unroll
        for (int k = 0; k < 16; k++) {
            const float r = pr[k * 32]; Gr[k] = pack2(r, r);
            const float u = pi[k * 32]; Gi[k] = pack2(u, u);
        }
    }
    __syncthreads();

    float* ob = out + (size_t)blk * 8192;
#pragma unroll 1
    for (int j = 0; j < 8; j++) k5_body(stw, Gr, Gi, ob, wg + 8 * j, co);
    if (wg == 0) k5_body(stw, Gr, Gi, ob, 64, co);
}

// ---------------------------------------------------------------------------
extern "C" void kernel_launch(void* const* d_in, const int* in_sizes, int n_in,
                              void* d_out, int out_size) {
    (void)n_in; (void)out_size; (void)in_sizes;
    const float* x  = (const float*)d_in[0];
    const float* wr = (const float*)d_in[1];
    const float* wi = (const float*)d_in[2];
    float* out = (float*)d_out;

    kA<<<2561, 128>>>(x, wr, wi);
    k2_dft_h<<<dim3(16, 2, 8), 136>>>();
    k3_mix<<<dim3(16, 32), 256>>>();
    k4_idft_h<<<dim3(4, 8, 8), 256>>>();
    k5_idft_w<<<2048, 256>>>(out);
}